// round 17
// baseline (speedup 1.0000x reference)
#include <cuda_runtime.h>
#include <cooperative_groups.h>
#include <math.h>

namespace cg = cooperative_groups;

#define KK 128
#define NNODES 2048
#define DD 512
#define NSPLIT 8

__device__ float g_p1[NSPLIT * KK * DD];   // split-K partials of ctx @ Wq^T
__device__ float g_p2[NSPLIT * KK * DD];   // split-K partials of cq @ Wk
__device__ int   g_mask_i32;

// ---------------------------------------------------------------------------
// Register-tiled split-K projection GEMMs, 8-way split (m-slice 64).
// Grid 256 = 8 ntiles(64) x 4 ktiles(32) x 8 splits. Block 128 threads.
// Thread = (kq 0..7, nq 0..15) owns 4k x 4n outputs. Inner loop: 16 mg groups.
//   STAGE1==false: A = ctx, B = Wq (NT) -> g_p1[sp]
//   STAGE1==true : A = sum_s g_p1[s], B = Wk (NN) -> g_p2[sp]
// Stage-1 block 0 also probes mask dtype (512 words all in {0,1} => int32).
// ---------------------------------------------------------------------------
template<bool STAGE1>
__global__ void __launch_bounds__(128) proj_gemm_rt(const float* __restrict__ Ain,
                                                    const float* __restrict__ B,
                                                    const int* __restrict__ m32) {
    __shared__ float As[32][68];
    __shared__ float BsA[STAGE1 ? 1 : 64][STAGE1 ? 1 : 68];   // stage1: [n][m]
    __shared__ float BsB[STAGE1 ? 64 : 1][STAGE1 ? 68 : 1];   // stage2: [m][n]

    const int t   = threadIdx.x;
    const int bx  = blockIdx.x;
    const int nt  = (bx & 7) * 64;
    const int ktb = ((bx >> 3) & 3) * 32;
    const int sp  = bx >> 5;                      // 0..7
    const int mt  = sp * 64;
    const int kq  = t >> 4;
    const int nq  = t & 15;

    if (!STAGE1 && bx == 0) {
        int v0 = m32[t], v1 = m32[t + 128], v2 = m32[t + 256], v3 = m32[t + 384];
        bool bad = (v0 | v1 | v2 | v3) >> 1;
        bool any = __syncthreads_or(bad);
        if (t == 0) g_mask_i32 = any ? 0 : 1;
    }

    // ---- As: 32 x 64 floats = 512 float4 (4/thread), coalesced ----
#pragma unroll
    for (int s = 0; s < 4; ++s) {
        int idx = t + s * 128;                    // 0..511
        int r = idx >> 4, c4 = idx & 15;
        if (!STAGE1) {
            *reinterpret_cast<float4*>(&As[r][c4 * 4]) =
                *reinterpret_cast<const float4*>(Ain + (ktb + r) * DD + mt + c4 * 4);
        } else {
            const int off = (ktb + r) * DD + mt + c4 * 4;
            float4 acc4 = *reinterpret_cast<const float4*>(g_p1 + off);
#pragma unroll
            for (int p = 1; p < NSPLIT; ++p) {
                float4 v = *reinterpret_cast<const float4*>(g_p1 + p * KK * DD + off);
                acc4.x += v.x; acc4.y += v.y; acc4.z += v.z; acc4.w += v.w;
            }
            *reinterpret_cast<float4*>(&As[r][c4 * 4]) = acc4;
        }
    }
    // ---- Bs: 64 x 64 floats = 1024 float4 (8/thread), coalesced ----
#pragma unroll
    for (int s = 0; s < 8; ++s) {
        int idx = t + s * 128;                    // 0..1023
        int r = idx >> 4, c4 = idx & 15;
        if (!STAGE1) {                            // BsA[n][m] = Wq[nt+n][mt+m]
            *reinterpret_cast<float4*>(&BsA[r][c4 * 4]) =
                *reinterpret_cast<const float4*>(B + (nt + r) * DD + mt + c4 * 4);
        } else {                                  // BsB[m][n] = Wk[mt+m][nt+n]
            *reinterpret_cast<float4*>(&BsB[r][c4 * 4]) =
                *reinterpret_cast<const float4*>(B + (mt + r) * DD + nt + c4 * 4);
        }
    }
    __syncthreads();

    float acc[4][4];
#pragma unroll
    for (int i = 0; i < 4; ++i)
#pragma unroll
        for (int j = 0; j < 4; ++j) acc[i][j] = 0.f;

#pragma unroll 4
    for (int mg = 0; mg < 16; ++mg) {
        float4 a0 = *reinterpret_cast<const float4*>(&As[4 * kq + 0][4 * mg]);
        float4 a1 = *reinterpret_cast<const float4*>(&As[4 * kq + 1][4 * mg]);
        float4 a2 = *reinterpret_cast<const float4*>(&As[4 * kq + 2][4 * mg]);
        float4 a3 = *reinterpret_cast<const float4*>(&As[4 * kq + 3][4 * mg]);
        float4 av[4] = {a0, a1, a2, a3};
        if (!STAGE1) {
            float4 b0 = *reinterpret_cast<const float4*>(&BsA[4 * nq + 0][4 * mg]);
            float4 b1 = *reinterpret_cast<const float4*>(&BsA[4 * nq + 1][4 * mg]);
            float4 b2 = *reinterpret_cast<const float4*>(&BsA[4 * nq + 2][4 * mg]);
            float4 b3 = *reinterpret_cast<const float4*>(&BsA[4 * nq + 3][4 * mg]);
            float4 bv[4] = {b0, b1, b2, b3};
#pragma unroll
            for (int i = 0; i < 4; ++i)
#pragma unroll
                for (int j = 0; j < 4; ++j)
                    acc[i][j] += av[i].x * bv[j].x + av[i].y * bv[j].y
                               + av[i].z * bv[j].z + av[i].w * bv[j].w;
        } else {
            float4 b0 = *reinterpret_cast<const float4*>(&BsB[4 * mg + 0][4 * nq]);
            float4 b1 = *reinterpret_cast<const float4*>(&BsB[4 * mg + 1][4 * nq]);
            float4 b2 = *reinterpret_cast<const float4*>(&BsB[4 * mg + 2][4 * nq]);
            float4 b3 = *reinterpret_cast<const float4*>(&BsB[4 * mg + 3][4 * nq]);
#pragma unroll
            for (int i = 0; i < 4; ++i) {
                acc[i][0] += av[i].x * b0.x + av[i].y * b1.x + av[i].z * b2.x + av[i].w * b3.x;
                acc[i][1] += av[i].x * b0.y + av[i].y * b1.y + av[i].z * b2.y + av[i].w * b3.y;
                acc[i][2] += av[i].x * b0.z + av[i].y * b1.z + av[i].z * b2.z + av[i].w * b3.z;
                acc[i][3] += av[i].x * b0.w + av[i].y * b1.w + av[i].z * b2.w + av[i].w * b3.w;
            }
        }
    }

    float* Out = (STAGE1 ? g_p2 : g_p1) + (size_t)sp * KK * DD;
#pragma unroll
    for (int i = 0; i < 4; ++i) {
        int k = ktb + 4 * kq + i;
        *reinterpret_cast<float4*>(Out + k * DD + nt + 4 * nq) =
            make_float4(acc[i][0], acc[i][1], acc[i][2], acc[i][3]);
    }
}

// ---------------------------------------------------------------------------
// Fused compat + masked softmax. One 2-CTA cluster per row k.
// Grid 256 x 512 threads, cluster (2,1,1): blockIdx.x>>1 = k, &1 = half.
// ---------------------------------------------------------------------------
__global__ void __launch_bounds__(512) __cluster_dims__(2, 1, 1)
compat_softmax(const float* __restrict__ nodep, const void* __restrict__ maskp,
               float* __restrict__ out) {
    __shared__ float evals[1024];
    __shared__ float wsums[16];
    __shared__ float ssum[2];

    cg::cluster_group cluster = cg::this_cluster();
    const unsigned rank = cluster.block_rank();
    const int lane = threadIdx.x & 31;
    const int w    = threadIdx.x >> 5;
    const int k    = blockIdx.x >> 1;
    const int half = blockIdx.x & 1;

    // q[k] = sum of NSPLIT stage-2 split partials (per-warp register copy)
    const float4* p2 = reinterpret_cast<const float4*>(g_p2);
    float4 q0, q1, q2, q3;
    {
        const int rs = DD / 4;
#pragma unroll
        for (int seg = 0; seg < 4; ++seg) {
            float4 q = p2[(size_t)k * rs + seg * 32 + lane];
#pragma unroll
            for (int p = 1; p < NSPLIT; ++p) {
                float4 v = p2[((size_t)p * KK + k) * rs + seg * 32 + lane];
                q.x += v.x; q.y += v.y; q.z += v.z; q.w += v.w;
            }
            if (seg == 0) q0 = q; else if (seg == 1) q1 = q;
            else if (seg == 2) q2 = q; else q3 = q;
        }
    }

    const bool mi32 = (g_mask_i32 != 0);
    float wacc = 0.f;

#pragma unroll
    for (int c = 0; c < 2; ++c) {
        const int nb = w * 64 + c * 32;
        const int i0 = half * 1024 + nb;

        bool msk;
        if (mi32) {
            msk = __ldg(reinterpret_cast<const int*>(maskp) + k * NNODES + i0 + lane) != 0;
        } else {
            msk = __ldg(reinterpret_cast<const unsigned char*>(maskp) + k * NNODES + i0 + lane) != 0;
        }

        const float4* base = reinterpret_cast<const float4*>(nodep)
                           + ((size_t)(k * NNODES + i0) << 7);

        float res = 0.f;
#pragma unroll 4
        for (int ii = 0; ii < 32; ++ii) {
            const float4* p = base + ((size_t)ii << 7);
            float4 v0 = __ldcs(p + lane);
            float4 v1 = __ldcs(p + 32 + lane);
            float4 v2 = __ldcs(p + 64 + lane);
            float4 v3 = __ldcs(p + 96 + lane);
            float a0 = v0.x * q0.x + v0.y * q0.y + v0.z * q0.z + v0.w * q0.w;
            float a1 = v1.x * q1.x + v1.y * q1.y + v1.z * q1.z + v1.w * q1.w;
            float a2 = v2.x * q2.x + v2.y * q2.y + v2.z * q2.z + v2.w * q2.w;
            float a3 = v3.x * q3.x + v3.y * q3.y + v3.z * q3.z + v3.w * q3.w;
            float a = (a0 + a1) + (a2 + a3);
#pragma unroll
            for (int off = 16; off; off >>= 1)
                a += __shfl_xor_sync(0xffffffffu, a, off);
            if (lane == ii) res = a;
        }

        float cl = fminf(10.f, fmaxf(-10.f, res));
        float v  = tanhf(cl) * 0.04419417382415922f;     // 1/sqrt(512)
        float e  = msk ? 0.f : __expf(v);
        evals[nb + lane] = e;

        float ws = e;
#pragma unroll
        for (int off = 16; off; off >>= 1)
            ws += __shfl_xor_sync(0xffffffffu, ws, off);
        wacc += ws;
    }

    if (lane == 0) wsums[w] = wacc;
    __syncthreads();

    if (w == 0) {
        float s = (lane < 16) ? wsums[lane] : 0.f;
#pragma unroll
        for (int off = 16; off; off >>= 1)
            s += __shfl_xor_sync(0xffffffffu, s, off);
        if (lane == 0) {
            ssum[rank] = s;
            float* peer = cluster.map_shared_rank(ssum, rank ^ 1u);
            peer[rank] = s;
        }
    }
    cluster.sync();

    const float inv = 1.0f / (ssum[0] + ssum[1]);
    const int t = threadIdx.x;
    float2 ev = *reinterpret_cast<const float2*>(&evals[2 * t]);
    float2* o2 = reinterpret_cast<float2*>(out + k * NNODES + half * 1024);
    o2[t] = make_float2(ev.x * inv, ev.y * inv);
}

extern "C" void kernel_launch(void* const* d_in, const int* in_sizes, int n_in,
                              void* d_out, int out_size) {
    const float* ctx  = (const float*)d_in[0];
    const float* node = (const float*)d_in[1];
    const void*  mask = d_in[2];
    const float* Wq   = (const float*)d_in[3];
    const float* Wk   = (const float*)d_in[4];
    float* out = (float*)d_out;
    (void)in_sizes; (void)n_in; (void)out_size;

    proj_gemm_rt<false><<<256, 128>>>(ctx, Wq, (const int*)mask);  // g_p1
    proj_gemm_rt<true ><<<256, 128>>>(nullptr, Wk, nullptr);       // g_p2
    compat_softmax<<<256, 512>>>(node, mask, out);                 // fused, clustered
}